// round 6
// baseline (speedup 1.0000x reference)
#include <cuda_runtime.h>

#define Bq 512
#define Tq 256
#define Fq 128
#define Hq 256
#define BTF (Bq*Tq*Fq)

typedef unsigned long long ull;

// ---------------- device scratch (no allocations allowed) ----------------
__device__ __align__(16) float g_WdhT[Fq*Hq];        // [k in F][j in H]
__device__ __align__(16) float g_WhT [Hq*Fq];        // [k in H][j in F]
__device__ __align__(16) float g_WfT [Fq*Fq];        // diag zeroed
__device__ __align__(16) float g_WcT [2*Fq*Fq];      // [k in 2F][j in F]
__device__ __align__(16) float g_WihT[2*Fq*4*Hq];    // [k in 2F][j in 4H]
__device__ __align__(16) float g_WhhT[Hq*4*Hq];      // [k in H][j in 4H]
__device__ float g_wdx[Fq];
__device__ float g_bsum[4*Hq];
__device__ float g_D[Tq];

// ---------------- packed f32x2 helpers ----------------
__device__ __forceinline__ ull pack2(float x, float y) {
    ull r; asm("mov.b64 %0, {%1,%2};" : "=l"(r) : "f"(x), "f"(y)); return r;
}
__device__ __forceinline__ void unpack2(ull v, float& x, float& y) {
    asm("mov.b64 {%0,%1}, %2;" : "=f"(x), "=f"(y) : "l"(v));
}
__device__ __forceinline__ ull ffma2(ull a, ull b, ull c) {
    ull d; asm("fma.rn.f32x2 %0, %1, %2, %3;" : "=l"(d) : "l"(a), "l"(b), "l"(c)); return d;
}

// ---------------- prep: transpose weights, diag, bias sum, zero scalars ----------------
__global__ void prep_weights(const float* __restrict__ Wdh, const float* __restrict__ Wh,
                             const float* __restrict__ Wf,  const float* __restrict__ Wc,
                             const float* __restrict__ Wih, const float* __restrict__ Whh,
                             const float* __restrict__ Wdx, const float* __restrict__ bih,
                             const float* __restrict__ bhh, float* __restrict__ out, int out_size)
{
    int i0 = blockIdx.x * blockDim.x + threadIdx.x;
    int stride = gridDim.x * blockDim.x;

    for (int idx = i0; idx < 1024*256; idx += stride) {
        int j = idx >> 8, k = idx & 255;
        g_WihT[k*1024 + j] = Wih[idx];
        g_WhhT[k*1024 + j] = Whh[idx];
    }
    for (int idx = i0; idx < 256*128; idx += stride) {
        int j = idx >> 7, k = idx & 127;
        g_WdhT[k*256 + j] = Wdh[idx];
    }
    for (int idx = i0; idx < 128*256; idx += stride) {
        int j = idx >> 8, k = idx & 255;
        g_WhT[k*128 + j] = Wh[idx];
        g_WcT[k*128 + j] = Wc[idx];
    }
    for (int idx = i0; idx < 128*128; idx += stride) {
        int j = idx >> 7, k = idx & 127;
        g_WfT[k*128 + j] = (j == k) ? 0.f : Wf[idx];
    }
    for (int idx = i0; idx < 128; idx += stride)  g_wdx[idx]  = Wdx[idx*128 + idx];
    for (int idx = i0; idx < 1024; idx += stride) g_bsum[idx] = bih[idx] + bhh[idx];
    for (int idx = i0; idx < 2; idx += stride)
        if (BTF + idx < out_size) out[BTF + idx] = 0.f;
}

// ---------------- per-timestep mask denominator ----------------
__global__ void mask_denom(const float* __restrict__ mask)
{
    int t = blockIdx.x;
    float s = 0.f;
    for (int i = threadIdx.x; i < Bq*Fq; i += blockDim.x) {
        int b = i >> 7, f = i & 127;
        s += mask[b*(Tq*Fq) + t*Fq + f];
    }
    for (int o = 16; o; o >>= 1) s += __shfl_down_sync(0xffffffffu, s, o);
    __shared__ float red[8];
    int lane = threadIdx.x & 31, wid = threadIdx.x >> 5;
    if (lane == 0) red[wid] = s;
    __syncthreads();
    if (threadIdx.x == 0) {
        float tt = 0.f;
        #pragma unroll
        for (int w = 0; w < 8; w++) tt += red[w];
        g_D[t] = tt;
    }
}

// GEMV accumulator for stage 6: act is [4][STR] in smem, wbase points at
// column-quad j0 of a [LEN][1024] transposed weight matrix. Accumulates into
// packed pairs a01 = {j0, j0+1}, a23 = {j0+2, j0+3} for 4 batch rows.
template<int LEN, int STR>
__device__ __forceinline__ void gemv_acc(const float* __restrict__ wbase,
                                         const float* __restrict__ act,
                                         ull a01[4], ull a23[4])
{
    #pragma unroll 2
    for (int k4 = 0; k4 < LEN; k4 += 4) {
        float4 iv[4];
        #pragma unroll
        for (int b = 0; b < 4; b++)
            iv[b] = *(const float4*)(act + b*STR + k4);
        #pragma unroll
        for (int kk = 0; kk < 4; kk++) {
            ulonglong2 w = *(const ulonglong2*)(wbase + (ull)(k4 + kk)*1024);
            #pragma unroll
            for (int b = 0; b < 4; b++) {
                float v = ((const float*)&iv[b])[kk];
                ull vp = pack2(v, v);
                a01[b] = ffma2(w.x, vp, a01[b]);
                a23[b] = ffma2(w.y, vp, a23[b]);
            }
        }
    }
}

// ---------------- main persistent kernel: 128 blocks x 512 threads x 4 rows ----------------
__global__ __launch_bounds__(512, 1)
void rits_persistent(const float* __restrict__ values, const float* __restrict__ mask,
                     const float* __restrict__ deltas,
                     const float* __restrict__ bdh, const float* __restrict__ bdx,
                     const float* __restrict__ bh,  const float* __restrict__ bf_,
                     const float* __restrict__ bc,  float* __restrict__ out, int out_size)
{
    __shared__ __align__(16) float sh[4][Hq], sc[4][Hq];
    __shared__ __align__(16) float sx[4][Fq], smk[4][Fq], sd[4][Fq];
    __shared__ __align__(16) float sgx[4][Fq], sxh[4][Fq], sxc[4][Fq], szh[4][Fq], scc[4][Fq];
    __shared__ __align__(16) float sgate[4][4*Hq];
    __shared__ float red1[16], red2[16], red3[16];

    const int tid = threadIdx.x;
    const int lane = tid & 31, wid = tid >> 5;
    const int rowBase = blockIdx.x * 4;

    for (int i = tid; i < 4*Hq; i += 512) { (&sh[0][0])[i] = 0.f; (&sc[0][0])[i] = 0.f; }
    __syncthreads();

    float xAcc = 0.f, mAcc = 0.f;   // tid 0 only
    float n1 = 0.f, n2 = 0.f;       // tid 0 only

    for (int t = 0; t < Tq; t++) {
        // ---- stage 1: load x, m, d; gamma_x (one element per thread) ----
        {
            int b = tid >> 7, f = tid & 127;
            int base = (rowBase + b)*(Tq*Fq) + t*Fq + f;
            float xv = values[base], mv = mask[base], dv = deltas[base];
            sx[b][f] = xv; smk[b][f] = mv; sd[b][f] = dv;
            sgx[b][f] = expf(-fmaxf(dv * g_wdx[f] + bdx[f], 0.f));
        }
        __syncthreads();

        // ---- stage 2: gamma_h, decay h (thread owns (j, row-pair)) ----
        {
            int j = tid & 255, half = tid >> 8;
            int b0 = 2*half, b1 = b0 + 1;
            float a0 = 0.f, a1 = 0.f;
            #pragma unroll 8
            for (int k = 0; k < Fq; k++) {
                float w = g_WdhT[k*Hq + j];
                a0 += w * sd[b0][k]; a1 += w * sd[b1][k];
            }
            float bb = bdh[j];
            sh[b0][j] *= expf(-fmaxf(a0 + bb, 0.f));
            sh[b1][j] *= expf(-fmaxf(a1 + bb, 0.f));
        }
        __syncthreads();

        // ---- stage 3: x_h = Wh @ h + bh; x_c; loss1 (one (f,b) per thread) ----
        {
            int f = tid & 127, b = tid >> 7;
            float a = 0.f;
            #pragma unroll 8
            for (int k = 0; k < Hq; k++)
                a += g_WhT[k*Fq + f] * sh[b][k];
            float xh = a + bh[f];
            sxh[b][f] = xh;
            float m = smk[b][f], x = sx[b][f];
            sxc[b][f] = m*x + (1.f - m)*xh;
            float l = fabsf(xh - x)*m;
            for (int o = 16; o; o >>= 1) l += __shfl_down_sync(0xffffffffu, l, o);
            if (lane == 0) red1[wid] = l;
        }
        __syncthreads();
        if (tid == 0) { n1 = 0.f; for (int w = 0; w < 16; w++) n1 += red1[w]; }

        // ---- stage 4: z_h = Wf_masked @ x_c + bf; loss2 ----
        {
            int f = tid & 127, b = tid >> 7;
            float a = 0.f;
            #pragma unroll 8
            for (int k = 0; k < Fq; k++)
                a += g_WfT[k*Fq + f] * sxc[b][k];
            float zh = a + bf_[f];
            szh[b][f] = zh;
            float m = smk[b][f], x = sx[b][f];
            float l = fabsf(zh - x)*m;
            for (int o = 16; o; o >>= 1) l += __shfl_down_sync(0xffffffffu, l, o);
            if (lane == 0) red2[wid] = l;
        }
        __syncthreads();
        if (tid == 0) { n2 = 0.f; for (int w = 0; w < 16; w++) n2 += red2[w]; }

        // ---- stage 5: alpha, c_h, c_c (output), loss3 ----
        {
            int f = tid & 127, b = tid >> 7;
            float a = 0.f;
            #pragma unroll 8
            for (int k = 0; k < Fq; k++)
                a += g_WcT[k*Fq + f] * sgx[b][k];
            #pragma unroll 8
            for (int k = 0; k < Fq; k++)
                a += g_WcT[(Fq + k)*Fq + f] * smk[b][k];
            float al = a + bc[f];
            float ch = al*szh[b][f] + (1.f - al)*sxh[b][f];
            float m = smk[b][f], x = sx[b][f];
            float l = fabsf(ch - x)*m;
            float cc = m*x + (1.f - m)*ch;
            scc[b][f] = cc;
            out[(rowBase + b)*(Tq*Fq) + t*Fq + f] = cc;
            for (int o = 16; o; o >>= 1) l += __shfl_down_sync(0xffffffffu, l, o);
            if (lane == 0) red3[wid] = l;
        }
        __syncthreads();
        if (tid == 0) {
            float n3 = 0.f;
            for (int w = 0; w < 16; w++) n3 += red3[w];
            float inv = 1.f / (g_D[t] + 1e-9f);
            xAcc += (n1 + n2 + (float)(Tq - t)*n3) * inv;
            mAcc += n3 * inv;
        }

        // ---- stage 6: gates, split-K across two thread halves ----
        {
            int jq = tid & 255;
            int j0 = jq * 4;
            int kh = tid >> 8;
            ull a01[4], a23[4];
            #pragma unroll
            for (int b = 0; b < 4; b++) { a01[b] = 0ull; a23[b] = 0ull; }

            if (kh == 0) {
                gemv_acc<Fq, Fq>(&g_WihT[j0],           &scc[0][0], a01, a23);
                gemv_acc<Fq, Fq>(&g_WihT[Fq*1024 + j0], &smk[0][0], a01, a23);
                float bs0 = g_bsum[j0], bs1 = g_bsum[j0+1], bs2 = g_bsum[j0+2], bs3 = g_bsum[j0+3];
                #pragma unroll
                for (int b = 0; b < 4; b++) {
                    float g0, g1, g2, g3;
                    unpack2(a01[b], g0, g1);
                    unpack2(a23[b], g2, g3);
                    float4 gv; gv.x = g0 + bs0; gv.y = g1 + bs1; gv.z = g2 + bs2; gv.w = g3 + bs3;
                    *(float4*)&sgate[b][j0] = gv;
                }
            } else {
                gemv_acc<Hq, Hq>(&g_WhhT[j0], &sh[0][0], a01, a23);
            }
            __syncthreads();
            if (kh == 1) {
                #pragma unroll
                for (int b = 0; b < 4; b++) {
                    float g0, g1, g2, g3;
                    unpack2(a01[b], g0, g1);
                    unpack2(a23[b], g2, g3);
                    float4 gv = *(const float4*)&sgate[b][j0];
                    gv.x += g0; gv.y += g1; gv.z += g2; gv.w += g3;
                    *(float4*)&sgate[b][j0] = gv;
                }
            }
            __syncthreads();
        }

        // ---- stage 7: LSTM update (gate order i, f, g, o) ----
        {
            int u = tid & 255;
            int bp = (tid >> 8) * 2;
            #pragma unroll
            for (int bb = 0; bb < 2; bb++) {
                int b = bp + bb;
                float ig = sgate[b][u];
                float fg = sgate[b][Hq + u];
                float gg = sgate[b][2*Hq + u];
                float og = sgate[b][3*Hq + u];
                float si = 1.f / (1.f + expf(-ig));
                float sf = 1.f / (1.f + expf(-fg));
                float so = 1.f / (1.f + expf(-og));
                float tg = tanhf(gg);
                float cn = sf*sc[b][u] + si*tg;
                sc[b][u] = cn;
                sh[b][u] = so * tanhf(cn);
            }
        }
        __syncthreads();
    }

    if (tid == 0 && BTF + 1 < out_size) {
        atomicAdd(&out[BTF],     xAcc * (1.f / (Tq * 3.0f)));
        atomicAdd(&out[BTF + 1], mAcc * (1.f / (float)Tq));
    }
}

// ---------------- launch ----------------
extern "C" void kernel_launch(void* const* d_in, const int* in_sizes, int n_in,
                              void* d_out, int out_size)
{
    const float* values = (const float*)d_in[0];
    const float* mask   = (const float*)d_in[1];
    const float* deltas = (const float*)d_in[2];
    const float* Wdh    = (const float*)d_in[3];
    const float* bdh    = (const float*)d_in[4];
    const float* Wdx    = (const float*)d_in[5];
    const float* bdx    = (const float*)d_in[6];
    const float* Wh     = (const float*)d_in[7];
    const float* bh     = (const float*)d_in[8];
    const float* Wf     = (const float*)d_in[9];
    const float* bf_    = (const float*)d_in[10];
    const float* Wc     = (const float*)d_in[11];
    const float* bc     = (const float*)d_in[12];
    const float* Wih    = (const float*)d_in[13];
    const float* Whh    = (const float*)d_in[14];
    const float* bih    = (const float*)d_in[15];
    const float* bhh    = (const float*)d_in[16];
    float* out = (float*)d_out;

    prep_weights<<<256, 256>>>(Wdh, Wh, Wf, Wc, Wih, Whh, Wdx, bih, bhh, out, out_size);
    mask_denom<<<Tq, 256>>>(mask);
    rits_persistent<<<Bq/4, 512>>>(values, mask, deltas, bdh, bdx, bh, bf_, bc, out, out_size);
}

// round 7
// speedup vs baseline: 1.2951x; 1.2951x over previous
#include <cuda_runtime.h>
#include <cuda_fp16.h>

#define Bq 512
#define Tq 256
#define Fq 128
#define Hq 256
#define BTF (Bq*Tq*Fq)

typedef unsigned long long ull;

// ---------------- device scratch (no allocations allowed) ----------------
__device__ __align__(16) float g_WdhT[Fq*Hq];        // [k in F][j in H]  fp32
__device__ __align__(16) float g_WhT [Hq*Fq];        // [k in H][j in F]  fp32
__device__ __align__(16) float g_WfT [Fq*Fq];        // diag zeroed       fp32
__device__ __align__(16) float g_WcT [2*Fq*Fq];      // [k in 2F][j in F] fp32
__device__ __align__(16) __half g_WihT_h[2*Fq*4*Hq]; // [k in 2F][j in 4H] fp16
__device__ __align__(16) __half g_WhhT_h[Hq*4*Hq];   // [k in H][j in 4H]  fp16
__device__ float g_wdx[Fq];
__device__ float g_bsum[4*Hq];
__device__ float g_D[Tq];

// ---------------- packed f32x2 helpers ----------------
__device__ __forceinline__ ull pack2(float x, float y) {
    ull r; asm("mov.b64 %0, {%1,%2};" : "=l"(r) : "f"(x), "f"(y)); return r;
}
__device__ __forceinline__ void unpack2(ull v, float& x, float& y) {
    asm("mov.b64 {%0,%1}, %2;" : "=f"(x), "=f"(y) : "l"(v));
}
__device__ __forceinline__ ull ffma2(ull a, ull b, ull c) {
    ull d; asm("fma.rn.f32x2 %0, %1, %2, %3;" : "=l"(d) : "l"(a), "l"(b), "l"(c)); return d;
}

struct __align__(8) H4 { __half2 a, b; };

// ---------------- prep: transpose weights, diag, bias sum, zero scalars ----------------
__global__ void prep_weights(const float* __restrict__ Wdh, const float* __restrict__ Wh,
                             const float* __restrict__ Wf,  const float* __restrict__ Wc,
                             const float* __restrict__ Wih, const float* __restrict__ Whh,
                             const float* __restrict__ Wdx, const float* __restrict__ bih,
                             const float* __restrict__ bhh, float* __restrict__ out, int out_size)
{
    int i0 = blockIdx.x * blockDim.x + threadIdx.x;
    int stride = gridDim.x * blockDim.x;

    // Wih, Whh: [1024, 256] -> fp16 transposed [256, 1024]
    for (int idx = i0; idx < 1024*256; idx += stride) {
        int j = idx >> 8, k = idx & 255;
        g_WihT_h[k*1024 + j] = __float2half(Wih[idx]);
        g_WhhT_h[k*1024 + j] = __float2half(Whh[idx]);
    }
    // Wdh: [256, 128] -> [128, 256]
    for (int idx = i0; idx < 256*128; idx += stride) {
        int j = idx >> 7, k = idx & 127;
        g_WdhT[k*256 + j] = Wdh[idx];
    }
    // Wh, Wc: [128, 256] -> [256, 128]
    for (int idx = i0; idx < 128*256; idx += stride) {
        int j = idx >> 8, k = idx & 255;
        g_WhT[k*128 + j] = Wh[idx];
        g_WcT[k*128 + j] = Wc[idx];
    }
    // Wf: [128, 128] -> transpose, zero diagonal
    for (int idx = i0; idx < 128*128; idx += stride) {
        int j = idx >> 7, k = idx & 127;
        g_WfT[k*128 + j] = (j == k) ? 0.f : Wf[idx];
    }
    for (int idx = i0; idx < 128; idx += stride)  g_wdx[idx]  = Wdx[idx*128 + idx];
    for (int idx = i0; idx < 1024; idx += stride) g_bsum[idx] = bih[idx] + bhh[idx];
    for (int idx = i0; idx < 2; idx += stride)
        if (BTF + idx < out_size) out[BTF + idx] = 0.f;
}

// ---------------- per-timestep mask denominator ----------------
__global__ void mask_denom(const float* __restrict__ mask)
{
    int t = blockIdx.x;
    float s = 0.f;
    for (int i = threadIdx.x; i < Bq*Fq; i += blockDim.x) {
        int b = i >> 7, f = i & 127;
        s += mask[b*(Tq*Fq) + t*Fq + f];
    }
    for (int o = 16; o; o >>= 1) s += __shfl_down_sync(0xffffffffu, s, o);
    __shared__ float red[8];
    int lane = threadIdx.x & 31, wid = threadIdx.x >> 5;
    if (lane == 0) red[wid] = s;
    __syncthreads();
    if (threadIdx.x == 0) {
        float tt = 0.f;
        #pragma unroll
        for (int w = 0; w < 8; w++) tt += red[w];
        g_D[t] = tt;
    }
}

// fp16-weight GEMV accumulator: act [4][STR] smem, wbase -> column-quad j0 of a
// [LEN][1024] fp16 transposed matrix. Packed fp32 accumulation.
template<int LEN, int STR>
__device__ __forceinline__ void gemv_acc_h(const __half* __restrict__ wbase,
                                           const float* __restrict__ act,
                                           ull a01[4], ull a23[4])
{
    #pragma unroll 2
    for (int k4 = 0; k4 < LEN; k4 += 4) {
        float4 iv[4];
        #pragma unroll
        for (int b = 0; b < 4; b++)
            iv[b] = *(const float4*)(act + b*STR + k4);
        #pragma unroll
        for (int kk = 0; kk < 4; kk++) {
            H4 w = *(const H4*)(wbase + (k4 + kk)*1024);
            float2 w01 = __half22float2(w.a);
            float2 w23 = __half22float2(w.b);
            ull w01p = pack2(w01.x, w01.y);
            ull w23p = pack2(w23.x, w23.y);
            #pragma unroll
            for (int b = 0; b < 4; b++) {
                float v = ((const float*)&iv[b])[kk];
                ull vp = pack2(v, v);
                a01[b] = ffma2(w01p, vp, a01[b]);
                a23[b] = ffma2(w23p, vp, a23[b]);
            }
        }
    }
}

// ---------------- main persistent kernel: 128 blocks x 512 threads x 4 rows ----------------
__global__ __launch_bounds__(512, 1)
void rits_persistent(const float* __restrict__ values, const float* __restrict__ mask,
                     const float* __restrict__ deltas,
                     const float* __restrict__ bdh, const float* __restrict__ bdx,
                     const float* __restrict__ bh,  const float* __restrict__ bf_,
                     const float* __restrict__ bc,  float* __restrict__ out, int out_size)
{
    __shared__ __align__(16) float sh[4][Hq], sc[4][Hq];
    __shared__ __align__(16) float sx[4][Fq], smk[4][Fq], sd[4][Fq];
    __shared__ __align__(16) float sgx[4][Fq], sxh[4][Fq], sxc[4][Fq], szh[4][Fq], scc[4][Fq];
    __shared__ __align__(16) float sgate[4][4*Hq];
    __shared__ float red1[8], red2[8], red3[8];

    const int tid = threadIdx.x;
    const int lane = tid & 31, wid = tid >> 5;
    const int rowBase = blockIdx.x * 4;

    for (int i = tid; i < 4*Hq; i += 512) { (&sh[0][0])[i] = 0.f; (&sc[0][0])[i] = 0.f; }
    __syncthreads();

    float xAcc = 0.f, mAcc = 0.f;   // tid 0 only
    float n1 = 0.f, n2 = 0.f;       // tid 0 only

    for (int t = 0; t < Tq; t++) {
        // ---- stage 1: load x, m, d; gamma_x (one element per thread) ----
        {
            int b = tid >> 7, f = tid & 127;
            int base = (rowBase + b)*(Tq*Fq) + t*Fq + f;
            float xv = values[base], mv = mask[base], dv = deltas[base];
            sx[b][f] = xv; smk[b][f] = mv; sd[b][f] = dv;
            sgx[b][f] = expf(-fmaxf(dv * g_wdx[f] + bdx[f], 0.f));
        }
        __syncthreads();

        // ---- stage 2: gamma_h, decay h (thread owns (j, row-pair)) ----
        {
            int j = tid & 255, half = tid >> 8;
            int b0 = 2*half, b1 = b0 + 1;
            float a0 = 0.f, a1 = 0.f;
            #pragma unroll 8
            for (int k = 0; k < Fq; k++) {
                float w = g_WdhT[k*Hq + j];
                a0 += w * sd[b0][k]; a1 += w * sd[b1][k];
            }
            float bb = bdh[j];
            sh[b0][j] *= expf(-fmaxf(a0 + bb, 0.f));
            sh[b1][j] *= expf(-fmaxf(a1 + bb, 0.f));
        }
        __syncthreads();
        // h is now final for this step until stage 7; smk final since stage 1.

        const int jq = tid & 255;
        const int j0 = jq * 4;
        ull a01[4], a23[4];
        #pragma unroll
        for (int b = 0; b < 4; b++) { a01[b] = 0ull; a23[b] = 0ull; }

        if (tid >= 256) {
            // ===== group B: stream Whh @ h and Wih(mask half) concurrently with stages 3-5 =====
            gemv_acc_h<Hq, Hq>(&g_WhhT_h[j0], &sh[0][0], a01, a23);
            gemv_acc_h<Fq, Fq>(&g_WihT_h[Fq*1024 + j0], &smk[0][0], a01, a23);
        } else {
            // ===== group A (tid < 256): stages 3-5, each thread owns (f, 2 rows) =====
            const int f = tid & 127;
            const int b0 = (tid >> 7) * 2, b1 = b0 + 1;

            // ---- stage 3: x_h = Wh @ h + bh; x_c; loss1 ----
            {
                float a0 = 0.f, a1 = 0.f;
                #pragma unroll 8
                for (int k = 0; k < Hq; k++) {
                    float w = g_WhT[k*Fq + f];
                    a0 += w * sh[b0][k]; a1 += w * sh[b1][k];
                }
                float bb = bh[f];
                float xh0 = a0 + bb, xh1 = a1 + bb;
                sxh[b0][f] = xh0; sxh[b1][f] = xh1;
                float m0 = smk[b0][f], m1 = smk[b1][f];
                float x0 = sx[b0][f],  x1 = sx[b1][f];
                sxc[b0][f] = m0*x0 + (1.f - m0)*xh0;
                sxc[b1][f] = m1*x1 + (1.f - m1)*xh1;
                float l = fabsf(xh0 - x0)*m0 + fabsf(xh1 - x1)*m1;
                for (int o = 16; o; o >>= 1) l += __shfl_down_sync(0xffffffffu, l, o);
                if (lane == 0) red1[wid] = l;
            }
            asm volatile("bar.sync 1, 256;" ::: "memory");
            if (tid == 0) { n1 = 0.f; for (int w = 0; w < 8; w++) n1 += red1[w]; }

            // ---- stage 4: z_h = Wf_masked @ x_c + bf; loss2 ----
            {
                float a0 = 0.f, a1 = 0.f;
                #pragma unroll 8
                for (int k = 0; k < Fq; k++) {
                    float w = g_WfT[k*Fq + f];
                    a0 += w * sxc[b0][k]; a1 += w * sxc[b1][k];
                }
                float bb = bf_[f];
                float zh0 = a0 + bb, zh1 = a1 + bb;
                szh[b0][f] = zh0; szh[b1][f] = zh1;
                float m0 = smk[b0][f], m1 = smk[b1][f];
                float x0 = sx[b0][f],  x1 = sx[b1][f];
                float l = fabsf(zh0 - x0)*m0 + fabsf(zh1 - x1)*m1;
                for (int o = 16; o; o >>= 1) l += __shfl_down_sync(0xffffffffu, l, o);
                if (lane == 0) red2[wid] = l;
            }
            asm volatile("bar.sync 1, 256;" ::: "memory");
            if (tid == 0) { n2 = 0.f; for (int w = 0; w < 8; w++) n2 += red2[w]; }

            // ---- stage 5: alpha, c_h, c_c (output), loss3 ----
            {
                float a0 = 0.f, a1 = 0.f;
                #pragma unroll 8
                for (int k = 0; k < Fq; k++) {
                    float w = g_WcT[k*Fq + f];
                    a0 += w * sgx[b0][k]; a1 += w * sgx[b1][k];
                }
                #pragma unroll 8
                for (int k = 0; k < Fq; k++) {
                    float w = g_WcT[(Fq + k)*Fq + f];
                    a0 += w * smk[b0][k]; a1 += w * smk[b1][k];
                }
                float bb = bc[f];
                float al0 = a0 + bb, al1 = a1 + bb;
                float ch0 = al0*szh[b0][f] + (1.f - al0)*sxh[b0][f];
                float ch1 = al1*szh[b1][f] + (1.f - al1)*sxh[b1][f];
                float m0 = smk[b0][f], m1 = smk[b1][f];
                float x0 = sx[b0][f],  x1 = sx[b1][f];
                float l = fabsf(ch0 - x0)*m0 + fabsf(ch1 - x1)*m1;
                float cc0 = m0*x0 + (1.f - m0)*ch0;
                float cc1 = m1*x1 + (1.f - m1)*ch1;
                scc[b0][f] = cc0; scc[b1][f] = cc1;
                out[(rowBase + b0)*(Tq*Fq) + t*Fq + f] = cc0;
                out[(rowBase + b1)*(Tq*Fq) + t*Fq + f] = cc1;
                for (int o = 16; o; o >>= 1) l += __shfl_down_sync(0xffffffffu, l, o);
                if (lane == 0) red3[wid] = l;
            }
            asm volatile("bar.sync 1, 256;" ::: "memory");
            if (tid == 0) {
                float n3 = 0.f;
                for (int w = 0; w < 8; w++) n3 += red3[w];
                float inv = 1.f / (g_D[t] + 1e-9f);
                xAcc += (n1 + n2 + (float)(Tq - t)*n3) * inv;
                mAcc += n3 * inv;
            }

            // ---- group A finishes Wih @ c_c half, writes gates with bias ----
            gemv_acc_h<Fq, Fq>(&g_WihT_h[j0], &scc[0][0], a01, a23);
            float bs0 = g_bsum[j0], bs1 = g_bsum[j0+1], bs2 = g_bsum[j0+2], bs3 = g_bsum[j0+3];
            #pragma unroll
            for (int b = 0; b < 4; b++) {
                float g0, g1, g2, g3;
                unpack2(a01[b], g0, g1);
                unpack2(a23[b], g2, g3);
                float4 gv; gv.x = g0 + bs0; gv.y = g1 + bs1; gv.z = g2 + bs2; gv.w = g3 + bs3;
                *(float4*)&sgate[b][j0] = gv;
            }
        }
        __syncthreads();

        // ---- group B adds its partial into sgate ----
        if (tid >= 256) {
            #pragma unroll
            for (int b = 0; b < 4; b++) {
                float g0, g1, g2, g3;
                unpack2(a01[b], g0, g1);
                unpack2(a23[b], g2, g3);
                float4 gv = *(const float4*)&sgate[b][j0];
                gv.x += g0; gv.y += g1; gv.z += g2; gv.w += g3;
                *(float4*)&sgate[b][j0] = gv;
            }
        }
        __syncthreads();

        // ---- stage 7: LSTM update (gate order i, f, g, o) ----
        {
            int u = tid & 255;
            int bp = (tid >> 8) * 2;
            #pragma unroll
            for (int bb = 0; bb < 2; bb++) {
                int b = bp + bb;
                float ig = sgate[b][u];
                float fg = sgate[b][Hq + u];
                float gg = sgate[b][2*Hq + u];
                float og = sgate[b][3*Hq + u];
                float si = 1.f / (1.f + expf(-ig));
                float sf = 1.f / (1.f + expf(-fg));
                float so = 1.f / (1.f + expf(-og));
                float tg = tanhf(gg);
                float cn = sf*sc[b][u] + si*tg;
                sc[b][u] = cn;
                sh[b][u] = so * tanhf(cn);
            }
        }
        __syncthreads();
    }

    if (tid == 0 && BTF + 1 < out_size) {
        atomicAdd(&out[BTF],     xAcc * (1.f / (Tq * 3.0f)));
        atomicAdd(&out[BTF + 1], mAcc * (1.f / (float)Tq));
    }
}

// ---------------- launch ----------------
extern "C" void kernel_launch(void* const* d_in, const int* in_sizes, int n_in,
                              void* d_out, int out_size)
{
    const float* values = (const float*)d_in[0];
    const float* mask   = (const float*)d_in[1];
    const float* deltas = (const float*)d_in[2];
    const float* Wdh    = (const float*)d_in[3];
    const float* bdh    = (const float*)d_in[4];
    const float* Wdx    = (const float*)d_in[5];
    const float* bdx    = (const float*)d_in[6];
    const float* Wh     = (const float*)d_in[7];
    const float* bh     = (const float*)d_in[8];
    const float* Wf     = (const float*)d_in[9];
    const float* bf_    = (const float*)d_in[10];
    const float* Wc     = (const float*)d_in[11];
    const float* bc     = (const float*)d_in[12];
    const float* Wih    = (const float*)d_in[13];
    const float* Whh    = (const float*)d_in[14];
    const float* bih    = (const float*)d_in[15];
    const float* bhh    = (const float*)d_in[16];
    float* out = (float*)d_out;

    prep_weights<<<256, 256>>>(Wdh, Wh, Wf, Wc, Wih, Whh, Wdx, bih, bhh, out, out_size);
    mask_denom<<<Tq, 256>>>(mask);
    rits_persistent<<<Bq/4, 512>>>(values, mask, deltas, bdh, bdx, bh, bf_, bc, out, out_size);
}